// round 10
// baseline (speedup 1.0000x reference)
#include <cuda_runtime.h>
#include <cuda_fp16.h>
#include <cstdint>

// out = LeakyReLU( D^-1 * (A @ (X @ W^T)) + b ),  B=32, N=1024, F=128
//
// k_xw  : XW = X @ W^T fp16 mma. W cvt'd once -> fp16 smem [o][f] (non-trans
//         ldmatrix = B operand directly). X frags direct-LDG, staged in regs.
// k_main: C = A @ XW fp16 mma. A frags DIRECT LDG.64 from gmem (no smem),
//         staged one stage ahead; deg = rowsum(A) FADD on fp32 values before
//         conversion. B via 4-deep cp.async ring + ldmatrix.trans.

#define NEG_SLOPE 0.01f

__device__ __half g_xw[32u * 1024u * 128u];  // fp16 XW [m][o] (8 MB)

// ---------------- helpers ----------------
__device__ __forceinline__ uint32_t su32(const void* p) {
    uint32_t r;
    asm("{\n\t.reg .u64 t;\n\tcvta.to.shared.u64 t, %1;\n\tcvt.u32.u64 %0, t;\n\t}"
        : "=r"(r) : "l"(p));
    return r;
}
__device__ __forceinline__ void cp16(uint32_t dst, const void* src) {
    asm volatile("cp.async.cg.shared.global [%0], [%1], 16;" :: "r"(dst), "l"(src));
}
__device__ __forceinline__ void cp_commit() {
    asm volatile("cp.async.commit_group;" ::: "memory");
}
template <int N>
__device__ __forceinline__ void cp_wait() {
    asm volatile("cp.async.wait_group %0;" :: "n"(N) : "memory");
}
__device__ __forceinline__ void mma_f16(float* c, const uint32_t* a, const uint32_t* b) {
    asm volatile(
        "mma.sync.aligned.m16n8k16.row.col.f32.f16.f16.f32 "
        "{%0,%1,%2,%3}, {%4,%5,%6,%7}, {%8,%9}, {%0,%1,%2,%3};"
        : "+f"(c[0]), "+f"(c[1]), "+f"(c[2]), "+f"(c[3])
        : "r"(a[0]), "r"(a[1]), "r"(a[2]), "r"(a[3]), "r"(b[0]), "r"(b[1]));
}
__device__ __forceinline__ void ldmat4t(uint32_t* r, uint32_t addr) {
    asm volatile(
        "ldmatrix.sync.aligned.m8n8.x4.trans.shared.b16 {%0,%1,%2,%3}, [%4];"
        : "=r"(r[0]), "=r"(r[1]), "=r"(r[2]), "=r"(r[3]) : "r"(addr));
}
__device__ __forceinline__ void ldmat4(uint32_t* r, uint32_t addr) {
    asm volatile(
        "ldmatrix.sync.aligned.m8n8.x4.shared.b16 {%0,%1,%2,%3}, [%4];"
        : "=r"(r[0]), "=r"(r[1]), "=r"(r[2]), "=r"(r[3]) : "r"(addr));
}
__device__ __forceinline__ uint32_t pack_h2(float lo, float hi) {
    uint32_t r;
    asm("cvt.rn.f16x2.f32 %0, %2, %1;" : "=r"(r) : "f"(lo), "f"(hi));
    return r;
}
__device__ __forceinline__ float leaky(float v) {
    return (v >= 0.0f) ? v : NEG_SLOPE * v;
}

// =====================================================================
// k_xw: XW = X @ W^T (fp16 mma). grid=512 (m-tiles 64), 256 thr, 8 warps:
// wr=wid&3 (m16), wc=wid>>2 (n64). X frags direct LDG staged 1 step ahead.
// W resident fp16 smem [o][136] — non-trans ldmatrix gives B frags.
// =====================================================================
__global__ __launch_bounds__(256) void k_xw(const float* __restrict__ X,
                                            const float* __restrict__ W) {
    __shared__ __align__(16) __half Wh[128 * 136];

    const int tid = threadIdx.x, lane = tid & 31, wid = tid >> 5;
    const int g = lane >> 2, tig = lane & 3;
    const int wr = wid & 3, wc = wid >> 2;
    const int m0 = blockIdx.x * 64;

    const float* xbase = X + (size_t)(m0 + wr * 16 + g) * 128 + tig * 2;
    float2 u[4];
    auto ldX = [&](int s) {
        const float* p = xbase + s * 16;
        u[0] = *(const float2*)p;
        u[1] = *(const float2*)(p + 1024);   // row +8
        u[2] = *(const float2*)(p + 8);      // k +8
        u[3] = *(const float2*)(p + 1032);
    };
    ldX(0);

    // W -> fp16 smem [o][136], coalesced STS.128 (one time)
    {
        const float4* ws = (const float4*)(W + (tid >> 1) * 128 + (tid & 1) * 64);
        __half* dst = Wh + (tid >> 1) * 136 + (tid & 1) * 64;
#pragma unroll
        for (int j = 0; j < 16; j += 2) {
            float4 w0 = ws[j], w1 = ws[j + 1];
            uint4 v;
            v.x = pack_h2(w0.x, w0.y);
            v.y = pack_h2(w0.z, w0.w);
            v.z = pack_h2(w1.x, w1.y);
            v.w = pack_h2(w1.z, w1.w);
            *(uint4*)(dst + j * 4) = v;
        }
    }
    __syncthreads();

    float acc[8][4];
#pragma unroll
    for (int ni = 0; ni < 8; ni++)
#pragma unroll
        for (int q = 0; q < 4; q++) acc[ni][q] = 0.0f;

    const uint32_t wh_a = su32(Wh);
    // non-trans x4 address lanes: rows n = (lane&7) + ((lane>>4)&1)*8,
    // k halfword offset 8 for lanes 8-15/24-31.
    const int n_row = (lane & 7) + ((lane >> 4) & 1) * 8;
    const int k_off = ((lane >> 3) & 1) * 8;

    for (int s = 0; s < 8; s++) {
        uint32_t a[4];
#pragma unroll
        for (int q = 0; q < 4; q++) a[q] = pack_h2(u[q].x, u[q].y);
        if (s < 7) ldX(s + 1);
#pragma unroll
        for (int j = 0; j < 4; j++) {  // n16 tiles
            int nr = wc * 64 + j * 16 + n_row;
            uint32_t addr = wh_a + (uint32_t)(nr * 136 + s * 16 + k_off) * 2;
            uint32_t bfr[4];
            ldmat4(bfr, addr);
            mma_f16(acc[j * 2 + 0], a, &bfr[0]);
            mma_f16(acc[j * 2 + 1], a, &bfr[2]);
        }
    }

    // epilogue: fp16 [m][o]
    uint32_t* outp = (uint32_t*)g_xw;
    const int row = m0 + wr * 16 + g;
#pragma unroll
    for (int ni = 0; ni < 8; ni++) {
        int col2 = wc * 32 + ni * 4 + tig;
        outp[(size_t)row * 64 + col2] = pack_h2(acc[ni][0], acc[ni][1]);
        outp[(size_t)(row + 8) * 64 + col2] = pack_h2(acc[ni][2], acc[ni][3]);
    }
}

// =====================================================================
// k_main: per batch C = A @ XW (fp16 mma); grid (8,32), 256 thr, 8 warps
// (wr=wid&3: m32, wc=wid>>2: n64). A frags direct LDG, staged 1 stage ahead.
// B: 4-deep cp.async ring [32 k][136 n-halves] + ldmatrix.trans.
// =====================================================================
__global__ __launch_bounds__(256, 2) void k_main(const float* __restrict__ A,
                                                 const float* __restrict__ bias,
                                                 float* __restrict__ out) {
    __shared__ __align__(16) char bsm[4 * 8704];
    __shared__ float degs[128];
    const uint32_t bs_a = su32(bsm);

    const int tid = threadIdx.x, lane = tid & 31, wid = tid >> 5;
    const int g = lane >> 2, tig = lane & 3;
    const int wr = wid & 3, wc = wid >> 2;
    const int m0 = blockIdx.x * 128, bz = blockIdx.y;
    const float* Ab = A + (size_t)bz * 1024 * 1024;
    const __half* Bp = g_xw + (size_t)bz * 131072;

    auto loadB = [&](int buf, int s) {
        const char* src = (const char*)(Bp + s * 4096);
#pragma unroll
        for (int i = 0; i < 2; i++) {
            int gi = tid + i * 256;
            int r = gi >> 4, c = gi & 15;
            cp16(bs_a + (uint32_t)(buf * 8704 + r * 272 + c * 16),
                 src + r * 256 + c * 16);
        }
        cp_commit();
    };

    const float* abase = Ab + (size_t)(m0 + wr * 32 + g) * 1024 + tig * 2;
    float2 u[2][2][4];  // [mi][h][q]
    auto ldA = [&](int s) {
#pragma unroll
        for (int mi = 0; mi < 2; mi++)
#pragma unroll
            for (int h = 0; h < 2; h++) {
                const float* p = abase + mi * 16384 + s * 32 + h * 16;
                u[mi][h][0] = *(const float2*)p;
                u[mi][h][1] = *(const float2*)(p + 8192);
                u[mi][h][2] = *(const float2*)(p + 8);
                u[mi][h][3] = *(const float2*)(p + 8200);
            }
    };

    float acc[2][8][4];
#pragma unroll
    for (int mi = 0; mi < 2; mi++)
#pragma unroll
        for (int ni = 0; ni < 8; ni++)
#pragma unroll
            for (int q = 0; q < 4; q++) acc[mi][ni][q] = 0.0f;
    float dg[2][2] = {{0.0f, 0.0f}, {0.0f, 0.0f}};

    loadB(0, 0);
    loadB(1, 1);
    loadB(2, 2);
    ldA(0);

    const int lm_k = lane & 15;
    const int lm_n8 = (lane >> 4) * 8;

    for (int s = 0; s < 32; s++) {
        __syncthreads();  // all warps done reading buf[(s+3)&3] (= stage s-1)
        if (s + 3 < 32) loadB((s + 3) & 3, s + 3);
        if (s < 29) cp_wait<3>();
        else if (s == 29) cp_wait<2>();
        else if (s == 30) cp_wait<1>();
        else cp_wait<0>();

        // pack A frags + degree from fp32 values, then reuse u for next stage
        uint32_t a[2][2][4];
#pragma unroll
        for (int mi = 0; mi < 2; mi++)
#pragma unroll
            for (int h = 0; h < 2; h++) {
                a[mi][h][0] = pack_h2(u[mi][h][0].x, u[mi][h][0].y);
                a[mi][h][1] = pack_h2(u[mi][h][1].x, u[mi][h][1].y);
                a[mi][h][2] = pack_h2(u[mi][h][2].x, u[mi][h][2].y);
                a[mi][h][3] = pack_h2(u[mi][h][3].x, u[mi][h][3].y);
                if (wc == 0) {
                    dg[mi][0] += (u[mi][h][0].x + u[mi][h][0].y) +
                                 (u[mi][h][2].x + u[mi][h][2].y);
                    dg[mi][1] += (u[mi][h][1].x + u[mi][h][1].y) +
                                 (u[mi][h][3].x + u[mi][h][3].y);
                }
            }
        if (s < 31) ldA(s + 1);

        const uint32_t bsb = bs_a + (s & 3) * 8704;
#pragma unroll
        for (int h = 0; h < 2; h++) {
            uint32_t bfr[4][4];
#pragma unroll
            for (int j = 0; j < 4; j++) {
                int n0 = wc * 64 + j * 16 + lm_n8;
                ldmat4t(bfr[j], bsb + (uint32_t)((h * 16 + lm_k) * 272 + n0 * 2));
            }
#pragma unroll
            for (int ni = 0; ni < 8; ni++) {
                const uint32_t* b = &bfr[ni >> 1][(ni & 1) * 2];
                mma_f16(acc[0][ni], a[0][h], b);
                mma_f16(acc[1][ni], a[1][h], b);
            }
        }
    }

    if (wc == 0) {
#pragma unroll
        for (int mi = 0; mi < 2; mi++)
#pragma unroll
            for (int r = 0; r < 2; r++) {
                float v = dg[mi][r];
                v += __shfl_xor_sync(0xffffffffu, v, 1);
                v += __shfl_xor_sync(0xffffffffu, v, 2);
                if (tig == 0) degs[wr * 32 + mi * 16 + r * 8 + g] = v;
            }
    }
    __syncthreads();

    float inv[2][2];
#pragma unroll
    for (int mi = 0; mi < 2; mi++) {
        inv[mi][0] = 1.0f / degs[wr * 32 + mi * 16 + g];
        inv[mi][1] = 1.0f / degs[wr * 32 + mi * 16 + g + 8];
    }

#pragma unroll
    for (int ni = 0; ni < 8; ni++) {
        int col = wc * 64 + ni * 8 + tig * 2;
        float2 bv = *(const float2*)(bias + col);
#pragma unroll
        for (int mi = 0; mi < 2; mi++) {
            int row = m0 + wr * 32 + mi * 16 + g;
            float2 v0, v1;
            v0.x = leaky(fmaf(acc[mi][ni][0], inv[mi][0], bv.x));
            v0.y = leaky(fmaf(acc[mi][ni][1], inv[mi][0], bv.y));
            v1.x = leaky(fmaf(acc[mi][ni][2], inv[mi][1], bv.x));
            v1.y = leaky(fmaf(acc[mi][ni][3], inv[mi][1], bv.y));
            *(float2*)(out + ((size_t)bz * 1024 + row) * 128 + col) = v0;
            *(float2*)(out + ((size_t)bz * 1024 + row + 8) * 128 + col) = v1;
        }
    }
}

// ---------------- host ----------------
extern "C" void kernel_launch(void* const* d_in, const int* in_sizes, int n_in,
                              void* d_out, int out_size) {
    const float* X    = (const float*)d_in[0];  // [32,1024,128]
    const float* adj  = (const float*)d_in[1];  // [32,1024,1024]
    const float* W    = (const float*)d_in[2];  // [128,128]
    const float* bias = (const float*)d_in[3];  // [128]
    float* out = (float*)d_out;                 // [32,1024,128]

    k_xw<<<512, 256>>>(X, W);
    k_main<<<dim3(8, 32), 256>>>(adj, bias, out);
}

// round 12
// speedup vs baseline: 1.3190x; 1.3190x over previous
#include <cuda_runtime.h>
#include <cuda_fp16.h>
#include <cstdint>

// out = LeakyReLU( D^-1 * (A @ (X @ W^T)) + b ),  B=32, N=1024, F=128
//
// wconv : W fp32 -> g_wh fp16 [o][f] (once).
// k_xw  : XW = X @ W^T fp16 mma. Whole X tile + Wh resident in smem (one
//         sync), B frags via non-trans ldmatrix from Wh. Output fp16 [m][o].
// k_main: C = A @ XW fp16 mma, 3-stage cp.async pipeline (R9, proven).
//         deg = rowsum(A) FADD on fp32 values; epilogue leaky(C/deg + b).

#define NEG_SLOPE 0.01f

__device__ __half g_xw[32u * 1024u * 128u];  // fp16 XW [m][o] (8 MB)
__device__ __half g_wh[128 * 128];           // fp16 W [o][f]

// ---------------- helpers ----------------
__device__ __forceinline__ uint32_t su32(const void* p) {
    uint32_t r;
    asm("{\n\t.reg .u64 t;\n\tcvta.to.shared.u64 t, %1;\n\tcvt.u32.u64 %0, t;\n\t}"
        : "=r"(r) : "l"(p));
    return r;
}
__device__ __forceinline__ void cp16(uint32_t dst, const void* src) {
    asm volatile("cp.async.cg.shared.global [%0], [%1], 16;" :: "r"(dst), "l"(src));
}
__device__ __forceinline__ void cp_commit() {
    asm volatile("cp.async.commit_group;" ::: "memory");
}
template <int N>
__device__ __forceinline__ void cp_wait() {
    asm volatile("cp.async.wait_group %0;" :: "n"(N) : "memory");
}
__device__ __forceinline__ void mma_f16(float* c, const uint32_t* a, const uint32_t* b) {
    asm volatile(
        "mma.sync.aligned.m16n8k16.row.col.f32.f16.f16.f32 "
        "{%0,%1,%2,%3}, {%4,%5,%6,%7}, {%8,%9}, {%0,%1,%2,%3};"
        : "+f"(c[0]), "+f"(c[1]), "+f"(c[2]), "+f"(c[3])
        : "r"(a[0]), "r"(a[1]), "r"(a[2]), "r"(a[3]), "r"(b[0]), "r"(b[1]));
}
__device__ __forceinline__ void ldmat4t(uint32_t* r, uint32_t addr) {
    asm volatile(
        "ldmatrix.sync.aligned.m8n8.x4.trans.shared.b16 {%0,%1,%2,%3}, [%4];"
        : "=r"(r[0]), "=r"(r[1]), "=r"(r[2]), "=r"(r[3]) : "r"(addr));
}
__device__ __forceinline__ void ldmat4(uint32_t* r, uint32_t addr) {
    asm volatile(
        "ldmatrix.sync.aligned.m8n8.x4.shared.b16 {%0,%1,%2,%3}, [%4];"
        : "=r"(r[0]), "=r"(r[1]), "=r"(r[2]), "=r"(r[3]) : "r"(addr));
}
__device__ __forceinline__ uint32_t pack_h2(float lo, float hi) {
    uint32_t r;
    asm("cvt.rn.f16x2.f32 %0, %2, %1;" : "=r"(r) : "f"(lo), "f"(hi));
    return r;
}
__device__ __forceinline__ float leaky(float v) {
    return (v >= 0.0f) ? v : NEG_SLOPE * v;
}

#define AP 40  // k_main A pad (floats): LDS.64 frag pairs conflict-free

// =====================================================================
// wconv: W fp32 [128][128] -> g_wh fp16. grid 16 x 256 threads.
// =====================================================================
__global__ void wconv(const float* __restrict__ W) {
    int idx = blockIdx.x * 256 + threadIdx.x;  // float4 index, 0..4095
    float4 w = ((const float4*)W)[idx];
    uint2 v;
    v.x = pack_h2(w.x, w.y);
    v.y = pack_h2(w.z, w.w);
    ((uint2*)g_wh)[idx] = v;
}

// =====================================================================
// k_xw: XW = X @ W^T (fp16 mma). grid=512 (m-tiles 64), 256 thr, 8 warps:
// wr=wid&3 (m16 each), wc=wid>>2 (n64 each). Whole tiles resident:
// smem: Wh fp16 [128][136] (34816B) | Xs fp32 [64][136] (34816B).
// =====================================================================
#define XW_SMEM (34816 + 34816)

__global__ __launch_bounds__(256) void k_xw(const float* __restrict__ X) {
    extern __shared__ char smx[];
    const uint32_t wh_a = su32(smx), xs_a = su32(smx + 34816);
    const float2* Xs2 = (const float2*)(smx + 34816);

    const int tid = threadIdx.x, lane = tid & 31, wid = tid >> 5;
    const int g = lane >> 2, tig = lane & 3;
    const int wr = wid & 3, wc = wid >> 2;
    const int m0 = blockIdx.x * 64;

    // Wh: 128 rows x 16 chunks(16B) at 272B stride
#pragma unroll
    for (int i = 0; i < 8; i++) {
        int ch = tid + i * 256;
        int r = ch >> 4, c = ch & 15;
        cp16(wh_a + (uint32_t)(r * 272 + c * 16), (const char*)g_wh + r * 256 + c * 16);
    }
    // Xs: 64 rows x 32 chunks(16B) at 544B stride
#pragma unroll
    for (int i = 0; i < 8; i++) {
        int ch = tid + i * 256;
        int r = ch >> 5, c = ch & 31;
        cp16(xs_a + (uint32_t)(r * 544 + c * 16),
             X + (size_t)(m0 + r) * 128 + c * 4);
    }
    cp_commit();
    cp_wait<0>();
    __syncthreads();

    float acc[8][4];
#pragma unroll
    for (int ni = 0; ni < 8; ni++)
#pragma unroll
        for (int q = 0; q < 4; q++) acc[ni][q] = 0.0f;

    // non-trans ldmatrix lane addressing (validated in R10):
    const int n_row = (lane & 7) + ((lane >> 4) & 1) * 8;
    const int k_off = ((lane >> 3) & 1) * 8;

#pragma unroll
    for (int s = 0; s < 8; s++) {
        // A frags: LDS.64 from Xs (stride 68 float2, conflict-free)
        int base = (wr * 16 + g) * 68 + s * 8 + tig;
        float2 u0 = Xs2[base];
        float2 u1 = Xs2[base + 8 * 68];
        float2 u2 = Xs2[base + 4];
        float2 u3 = Xs2[base + 8 * 68 + 4];
        uint32_t a[4] = {pack_h2(u0.x, u0.y), pack_h2(u1.x, u1.y),
                         pack_h2(u2.x, u2.y), pack_h2(u3.x, u3.y)};
#pragma unroll
        for (int j = 0; j < 4; j++) {  // n16 tiles
            int nr = wc * 64 + j * 16 + n_row;
            uint32_t addr = wh_a + (uint32_t)(nr * 136 + s * 16 + k_off) * 2;
            uint32_t bfr[4];
            ldmat4(bfr, addr);
            mma_f16(acc[j * 2 + 0], a, &bfr[0]);
            mma_f16(acc[j * 2 + 1], a, &bfr[2]);
        }
    }

    // epilogue: fp16 [m][o] (validated in R10)
    uint32_t* outp = (uint32_t*)g_xw;
    const int row = m0 + wr * 16 + g;
#pragma unroll
    for (int ni = 0; ni < 8; ni++) {
        int col2 = wc * 32 + ni * 4 + tig;
        outp[(size_t)row * 64 + col2] = pack_h2(acc[ni][0], acc[ni][1]);
        outp[(size_t)(row + 8) * 64 + col2] = pack_h2(acc[ni][2], acc[ni][3]);
    }
}

// =====================================================================
// k_main (R9, proven 43.3us): per batch C = A @ XW, 3-stage pipeline.
// smem: As 3 x [128][40] fp32 (61440B) | Bs 3 x [32][136] fp16 (26112B)
// =====================================================================
#define AS3 61440
#define BS3 26112
#define MAIN_SMEM (AS3 + BS3 + 512)

__global__ __launch_bounds__(256, 2) void k_main(const float* __restrict__ A,
                                                 const float* __restrict__ bias,
                                                 float* __restrict__ out) {
    extern __shared__ float sm[];
    char* smc = (char*)sm;
    const float2* As2 = (const float2*)sm;
    float* degs = (float*)(smc + AS3 + BS3);
    const uint32_t as_a = su32(sm), bs_a = su32(smc + AS3);

    const int tid = threadIdx.x, lane = tid & 31, wid = tid >> 5;
    const int g = lane >> 2, tig = lane & 3;
    const int wr = wid & 3, wc = wid >> 2;
    const int m0 = blockIdx.x * 128, bz = blockIdx.y;
    const float* Ab = A + (size_t)bz * 1024 * 1024;
    const __half* Bp = g_xw + (size_t)bz * 131072;

    const int lr = tid >> 3, lc4 = tid & 7;

    auto loadT = [&](int buf, int s) {
#pragma unroll
        for (int i = 0; i < 4; i++) {
            int row = lr + i * 32;
            cp16(as_a + (uint32_t)((buf * 128 + row) * AP + lc4 * 4) * 4,
                 Ab + (size_t)(m0 + row) * 1024 + s * 32 + lc4 * 4);
        }
        const char* src = (const char*)(Bp + s * 32 * 128);
#pragma unroll
        for (int i = 0; i < 2; i++) {
            int gi = tid + i * 256;
            int r = gi >> 4, c = gi & 15;
            cp16(bs_a + (uint32_t)(buf * 8704 + r * 272 + c * 16),
                 src + r * 256 + c * 16);
        }
        cp_commit();
    };

    float acc[2][8][4];
#pragma unroll
    for (int mi = 0; mi < 2; mi++)
#pragma unroll
        for (int ni = 0; ni < 8; ni++)
#pragma unroll
            for (int q = 0; q < 4; q++) acc[mi][ni][q] = 0.0f;
    float dg[2][2] = {{0.0f, 0.0f}, {0.0f, 0.0f}};

    loadT(0, 0);
    loadT(1, 1);

    const int lm_k = lane & 15;
    const int lm_n8 = (lane >> 4) * 8;

    int buf = 0;
    for (int s = 0; s < 32; s++) {
        if (s < 30) {
            loadT(buf == 0 ? 2 : buf - 1, s + 2);  // (s+2)%3
            cp_wait<2>();
        } else if (s == 30) cp_wait<1>();
        else cp_wait<0>();
        __syncthreads();
        const uint32_t bsb = bs_a + buf * 8704;

#pragma unroll
        for (int h = 0; h < 2; h++) {
            uint32_t a[2][4];
#pragma unroll
            for (int mi = 0; mi < 2; mi++) {
                int row = wr * 32 + mi * 16 + g;
                int base = (buf * 128 + row) * (AP / 2) + h * 8 + tig;
                float2 u0 = As2[base];
                float2 u1 = As2[base + 8 * (AP / 2)];
                float2 u2 = As2[base + 4];
                float2 u3 = As2[base + 8 * (AP / 2) + 4];
                a[mi][0] = pack_h2(u0.x, u0.y);
                a[mi][1] = pack_h2(u1.x, u1.y);
                a[mi][2] = pack_h2(u2.x, u2.y);
                a[mi][3] = pack_h2(u3.x, u3.y);
                if (wc == 0) {
                    dg[mi][0] += (u0.x + u0.y) + (u2.x + u2.y);
                    dg[mi][1] += (u1.x + u1.y) + (u3.x + u3.y);
                }
            }
            uint32_t bfr[4][4];
#pragma unroll
            for (int j = 0; j < 4; j++) {
                int n0 = wc * 64 + j * 16 + lm_n8;
                ldmat4t(bfr[j], bsb + (uint32_t)((h * 16 + lm_k) * 272 + n0 * 2));
            }
#pragma unroll
            for (int ni = 0; ni < 8; ni++) {
                const uint32_t* b = &bfr[ni >> 1][(ni & 1) * 2];
                mma_f16(acc[0][ni], a[0], b);
                mma_f16(acc[1][ni], a[1], b);
            }
        }
        __syncthreads();
        buf = (buf == 2) ? 0 : buf + 1;
    }

    if (wc == 0) {
#pragma unroll
        for (int mi = 0; mi < 2; mi++)
#pragma unroll
            for (int r = 0; r < 2; r++) {
                float v = dg[mi][r];
                v += __shfl_xor_sync(0xffffffffu, v, 1);
                v += __shfl_xor_sync(0xffffffffu, v, 2);
                if (tig == 0) degs[wr * 32 + mi * 16 + r * 8 + g] = v;
            }
    }
    __syncthreads();

    float inv[2][2];
#pragma unroll
    for (int mi = 0; mi < 2; mi++) {
        inv[mi][0] = 1.0f / degs[wr * 32 + mi * 16 + g];
        inv[mi][1] = 1.0f / degs[wr * 32 + mi * 16 + g + 8];
    }

#pragma unroll
    for (int ni = 0; ni < 8; ni++) {
        int col = wc * 64 + ni * 8 + tig * 2;
        float2 bv = *(const float2*)(bias + col);
#pragma unroll
        for (int mi = 0; mi < 2; mi++) {
            int row = m0 + wr * 32 + mi * 16 + g;
            float2 v0, v1;
            v0.x = leaky(fmaf(acc[mi][ni][0], inv[mi][0], bv.x));
            v0.y = leaky(fmaf(acc[mi][ni][1], inv[mi][0], bv.y));
            v1.x = leaky(fmaf(acc[mi][ni][2], inv[mi][1], bv.x));
            v1.y = leaky(fmaf(acc[mi][ni][3], inv[mi][1], bv.y));
            *(float2*)(out + ((size_t)bz * 1024 + row) * 128 + col) = v0;
            *(float2*)(out + ((size_t)bz * 1024 + row + 8) * 128 + col) = v1;
        }
    }
}

// ---------------- host ----------------
extern "C" void kernel_launch(void* const* d_in, const int* in_sizes, int n_in,
                              void* d_out, int out_size) {
    const float* X    = (const float*)d_in[0];  // [32,1024,128]
    const float* adj  = (const float*)d_in[1];  // [32,1024,1024]
    const float* W    = (const float*)d_in[2];  // [128,128]
    const float* bias = (const float*)d_in[3];  // [128]
    float* out = (float*)d_out;                 // [32,1024,128]

    static int inited = 0;
    if (!inited) {
        cudaFuncSetAttribute(k_xw, cudaFuncAttributeMaxDynamicSharedMemorySize, XW_SMEM);
        cudaFuncSetAttribute(k_main, cudaFuncAttributeMaxDynamicSharedMemorySize, MAIN_SMEM);
        inited = 1;
    }

    wconv<<<16, 256>>>(W);
    k_xw<<<512, 256, XW_SMEM>>>(X);
    k_main<<<dim3(8, 32), 256, MAIN_SMEM>>>(adj, bias, out);
}